// round 14
// baseline (speedup 1.0000x reference)
#include <cuda_runtime.h>
#include <cuda_fp16.h>
#include <cstdint>

namespace {
constexpr int B = 4, H = 16, S = 2048, D = 64;
constexpr int TQ = 128, TK = 64, NKT = S / TK;
constexpr float QSCALE = 0.18033688011112042f;   // (1/8) * log2(e): exp -> 2^x
constexpr int PIT = 72;                          // smem pitch (halves); 144B rows
// attn_norm smem: Q + 2xK + 2xV
constexpr int OFF_QH = 0;                        // [128][72]
constexpr int OFF_K  = OFF_QH + TQ * PIT;        // 2 buffers [64][72]
constexpr int OFF_V  = OFF_K + 2 * TK * PIT;
constexpr int SMEM_BYTES = (OFF_V + 2 * TK * PIT) * 2;   // 55,296 B -> occ 2
// lpass smem: Q + 2xK only
constexpr int SMEM_L_BYTES = (OFF_K + 2 * TK * PIT) * 2; // 36,864 B -> occ 3
constexpr size_t NE = (size_t)B * H * S * D;
}

__device__ float g_linv[B * H * S];              // 1/softmax-denominator
__device__ __half g_qh[NE];                      // Q scaled -> fp16
__device__ __half g_kh[NE], g_vh[NE];            // K, V rounded to fp16

// ── PTX building blocks (baseline PTX: family-target safe) ──
__device__ __forceinline__ void ldsm4(uint32_t r[4], uint32_t a) {
    asm volatile("ldmatrix.sync.aligned.m8n8.x4.shared.b16 {%0,%1,%2,%3}, [%4];"
                 : "=r"(r[0]), "=r"(r[1]), "=r"(r[2]), "=r"(r[3]) : "r"(a));
}
__device__ __forceinline__ void ldsm4t(uint32_t r[4], uint32_t a) {
    asm volatile("ldmatrix.sync.aligned.m8n8.x4.trans.shared.b16 {%0,%1,%2,%3}, [%4];"
                 : "=r"(r[0]), "=r"(r[1]), "=r"(r[2]), "=r"(r[3]) : "r"(a));
}
__device__ __forceinline__ void mma16816(float c[4], const uint32_t a[4],
                                         uint32_t b0, uint32_t b1) {
    asm volatile("mma.sync.aligned.m16n8k16.row.col.f32.f16.f16.f32 "
                 "{%0,%1,%2,%3}, {%4,%5,%6,%7}, {%8,%9}, {%0,%1,%2,%3};"
                 : "+f"(c[0]), "+f"(c[1]), "+f"(c[2]), "+f"(c[3])
                 : "r"(a[0]), "r"(a[1]), "r"(a[2]), "r"(a[3]), "r"(b0), "r"(b1));
}
__device__ __forceinline__ uint32_t smem_u32(const void* p) {
    uint32_t a;
    asm("{ .reg .u64 t; cvta.to.shared.u64 t, %1; cvt.u32.u64 %0, t; }" : "=r"(a) : "l"(p));
    return a;
}
__device__ __forceinline__ void cpasync16(uint32_t dst, const void* src) {
    asm volatile("cp.async.cg.shared.global [%0], [%1], 16;" :: "r"(dst), "l"(src) : "memory");
}
#define CP_COMMIT() asm volatile("cp.async.commit_group;" ::: "memory")
#define CP_WAIT1()  asm volatile("cp.async.wait_group 1;" ::: "memory")

__device__ __forceinline__ float ex2f(float x) {
    float r; asm("ex2.approx.ftz.f32 %0, %1;" : "=f"(r) : "f"(x)); return r;
}
__device__ __forceinline__ uint32_t pack2(float a, float b) {
    __half2 h = __floats2half2_rn(a, b);
    return *reinterpret_cast<uint32_t*>(&h);
}

// ── pre-convert: q (scaled) / k / v -> fp16 scratch (~20us, DRAM-bound) ──
__global__ __launch_bounds__(256)
void preconv(const float4* __restrict__ q, const float4* __restrict__ k,
             const float4* __restrict__ v)
{
    size_t i = (size_t)blockIdx.x * 256 + threadIdx.x;
    float4 x = q[i];
    ((uint32_t*)g_qh)[2*i]   = pack2(x.x * QSCALE, x.y * QSCALE);
    ((uint32_t*)g_qh)[2*i+1] = pack2(x.z * QSCALE, x.w * QSCALE);
    x = k[i];
    ((uint32_t*)g_kh)[2*i]   = pack2(x.x, x.y); ((uint32_t*)g_kh)[2*i+1] = pack2(x.z, x.w);
    x = v[i];
    ((uint32_t*)g_vh)[2*i]   = pack2(x.x, x.y); ((uint32_t*)g_vh)[2*i+1] = pack2(x.z, x.w);
}

// ── lpass: QK + mask + exp + row-sum -> g_linv. No V, no attn write. ──
__global__ __launch_bounds__(256, 3)
void lpass(const int* __restrict__ mask)
{
    extern __shared__ __half sm[];
    const uint32_t sbase = smem_u32(sm);
    const int tid = threadIdx.x;
    const int wid = tid >> 5, ln = tid & 31;
    const int g = ln >> 2, tg = ln & 3;
    const int qr = wid * 16;
    const int h = blockIdx.x, qt = blockIdx.y, b = blockIdx.z;
    const int bh = b * H + h;
    const int li = ln & 7, s1 = (ln >> 3) & 1, s2 = ln >> 4;

    auto issue_k = [&](int kt, int buf) {
        const __half* kg = g_kh + ((size_t)bh * S + (size_t)kt * TK) * D;
        #pragma unroll
        for (int i = 0; i < 2; i++) {
            int f = tid + i * 256;
            int row = f >> 3, ch = f & 7;
            cpasync16(sbase + (uint32_t)((OFF_K + buf * TK * PIT + row * PIT) * 2) + ch * 16,
                      kg + row * 64 + ch * 8);
        }
    };
    {
        const __half* qg = g_qh + ((size_t)bh * S + (size_t)qt * TQ) * D;
        #pragma unroll
        for (int i = 0; i < 4; i++) {
            int f = tid + i * 256;
            int row = f >> 3, ch = f & 7;
            cpasync16(sbase + (uint32_t)((OFF_QH + row * PIT) * 2) + ch * 16,
                      qg + row * 64 + ch * 8);
        }
    }
    issue_k(0, 0); CP_COMMIT();
    issue_k(1, 1); CP_COMMIT();
    CP_WAIT1();
    __syncthreads();

    uint32_t qh[4][4];
    {
        uint32_t ro = (uint32_t)((qr + li + 8 * s1) * PIT + 8 * s2) * 2;
        #pragma unroll
        for (int ks = 0; ks < 4; ks++)
            ldsm4(qh[ks], sbase + (uint32_t)OFF_QH * 2 + ro + 32 * ks);
    }

    float lsum0 = 0.f, lsum1 = 0.f;
    const int* mrow = mask + (size_t)b * S * S + (size_t)(qt * TQ + qr + g) * S;
    const uint32_t koff = (uint32_t)(li * PIT + 8 * s1 + 16 * s2) * 2;

    for (int kt = 0; kt < NKT; kt++) {
        const uint32_t cb = (uint32_t)((kt & 1) * TK * PIT) * 2;
        CP_WAIT1();
        __syncthreads();

        int2 m0r[8], m1r[8];
        #pragma unroll
        for (int nt = 0; nt < 8; nt++) {
            int c = kt * TK + nt * 8 + 2 * tg;
            m0r[nt] = *(const int2*)&mrow[c];
            m1r[nt] = *(const int2*)&mrow[(size_t)8 * S + c];
        }

        #pragma unroll
        for (int nt = 0; nt < 8; nt++) {
            float sacc[4] = {0.f, 0.f, 0.f, 0.f};
            uint32_t ka = sbase + (uint32_t)OFF_K * 2 + cb + koff + (uint32_t)(8 * nt * PIT) * 2;
            uint32_t kh0[4], kh1[4];
            ldsm4(kh0, ka);
            ldsm4(kh1, ka + 64);
            mma16816(sacc, qh[0], kh0[0], kh0[1]);
            mma16816(sacc, qh[1], kh0[2], kh0[3]);
            mma16816(sacc, qh[2], kh1[0], kh1[1]);
            mma16816(sacc, qh[3], kh1[2], kh1[3]);
            lsum0 += (m0r[nt].x ? ex2f(sacc[0]) : 0.f) + (m0r[nt].y ? ex2f(sacc[1]) : 0.f);
            lsum1 += (m1r[nt].x ? ex2f(sacc[2]) : 0.f) + (m1r[nt].y ? ex2f(sacc[3]) : 0.f);
        }

        __syncthreads();
        if (kt + 2 < NKT) issue_k(kt + 2, kt & 1);
        CP_COMMIT();
    }

    lsum0 += __shfl_xor_sync(0xffffffffu, lsum0, 1);
    lsum0 += __shfl_xor_sync(0xffffffffu, lsum0, 2);
    lsum1 += __shfl_xor_sync(0xffffffffu, lsum1, 1);
    lsum1 += __shfl_xor_sync(0xffffffffu, lsum1, 2);
    if (tg == 0) {
        const size_t gr0 = (size_t)bh * S + (size_t)(qt * TQ + qr + g);
        g_linv[gr0]     = 1.0f / lsum0;
        g_linv[gr0 + 8] = 1.0f / lsum1;
    }
}

// ── attn_norm: recompute S, write NORMALIZED fp32 attn directly, PV -> O ──
__global__ __launch_bounds__(256, 2)
void attn_norm(const int* __restrict__ mask, float* __restrict__ out,
               float* __restrict__ attn)
{
    extern __shared__ __half sm[];
    const uint32_t sbase = smem_u32(sm);
    const int tid = threadIdx.x;
    const int wid = tid >> 5, ln = tid & 31;
    const int g = ln >> 2, tg = ln & 3;
    const int qr = wid * 16;
    const int h = blockIdx.x, qt = blockIdx.y, b = blockIdx.z;
    const int bh = b * H + h;
    const int li = ln & 7, s1 = (ln >> 3) & 1, s2 = ln >> 4;

    auto issue_kv = [&](int kt, int buf) {
        const __half* kg = g_kh + ((size_t)bh * S + (size_t)kt * TK) * D;
        const __half* vg = g_vh + ((size_t)bh * S + (size_t)kt * TK) * D;
        #pragma unroll
        for (int i = 0; i < 2; i++) {
            int f = tid + i * 256;
            int row = f >> 3, ch = f & 7;
            cpasync16(sbase + (uint32_t)((OFF_K + buf * TK * PIT + row * PIT) * 2) + ch * 16,
                      kg + row * 64 + ch * 8);
            cpasync16(sbase + (uint32_t)((OFF_V + buf * TK * PIT + row * PIT) * 2) + ch * 16,
                      vg + row * 64 + ch * 8);
        }
    };
    {
        const __half* qg = g_qh + ((size_t)bh * S + (size_t)qt * TQ) * D;
        #pragma unroll
        for (int i = 0; i < 4; i++) {
            int f = tid + i * 256;
            int row = f >> 3, ch = f & 7;
            cpasync16(sbase + (uint32_t)((OFF_QH + row * PIT) * 2) + ch * 16,
                      qg + row * 64 + ch * 8);
        }
    }
    issue_kv(0, 0); CP_COMMIT();
    issue_kv(1, 1); CP_COMMIT();
    CP_WAIT1();
    __syncthreads();

    uint32_t qh[4][4];
    {
        uint32_t ro = (uint32_t)((qr + li + 8 * s1) * PIT + 8 * s2) * 2;
        #pragma unroll
        for (int ks = 0; ks < 4; ks++)
            ldsm4(qh[ks], sbase + (uint32_t)OFF_QH * 2 + ro + 32 * ks);
    }

    // per-row 1/l, known up front (lpass ran first)
    const size_t gr0 = (size_t)bh * S + (size_t)(qt * TQ + qr + g);
    const float inv0 = g_linv[gr0];
    const float inv1 = g_linv[gr0 + 8];

    float oacc[8][4];
    #pragma unroll
    for (int nt = 0; nt < 8; nt++)
        #pragma unroll
        for (int i = 0; i < 4; i++) oacc[nt][i] = 0.f;

    const int* mrow = mask + (size_t)b * S * S + (size_t)(qt * TQ + qr + g) * S;
    float*     arow = attn + gr0 * S;

    const uint32_t koff = (uint32_t)(li * PIT + 8 * s1 + 16 * s2) * 2;
    const uint32_t voff = (uint32_t)((li + 8 * s1) * PIT + 8 * s2) * 2;

    for (int kt = 0; kt < NKT; kt++) {
        const uint32_t cb = (uint32_t)((kt & 1) * TK * PIT) * 2;
        CP_WAIT1();
        __syncthreads();

        int2 m0r[8], m1r[8];
        #pragma unroll
        for (int nt = 0; nt < 8; nt++) {
            int c = kt * TK + nt * 8 + 2 * tg;
            m0r[nt] = *(const int2*)&mrow[c];
            m1r[nt] = *(const int2*)&mrow[(size_t)8 * S + c];
        }

        // ── S = Qh*Kh ──
        float sacc[8][4];
        #pragma unroll
        for (int nt = 0; nt < 8; nt++) {
            #pragma unroll
            for (int i = 0; i < 4; i++) sacc[nt][i] = 0.f;
            uint32_t ka = sbase + (uint32_t)OFF_K * 2 + cb + koff + (uint32_t)(8 * nt * PIT) * 2;
            uint32_t kh0[4], kh1[4];
            ldsm4(kh0, ka);
            ldsm4(kh1, ka + 64);
            mma16816(sacc[nt], qh[0], kh0[0], kh0[1]);
            mma16816(sacc[nt], qh[1], kh0[2], kh0[3]);
            mma16816(sacc[nt], qh[2], kh1[0], kh1[1]);
            mma16816(sacc[nt], qh[3], kh1[2], kh1[3]);
        }

        // ── mask, 2^s, normalize in fp32; write attn; pack normalized p for PV ──
        uint32_t pp[8][2];
        #pragma unroll
        for (int nt = 0; nt < 8; nt++) {
            int c = kt * TK + nt * 8 + 2 * tg;
            float p0 = (m0r[nt].x ? ex2f(sacc[nt][0]) : 0.f) * inv0;
            float p1 = (m0r[nt].y ? ex2f(sacc[nt][1]) : 0.f) * inv0;
            float p2 = (m1r[nt].x ? ex2f(sacc[nt][2]) : 0.f) * inv1;
            float p3 = (m1r[nt].y ? ex2f(sacc[nt][3]) : 0.f) * inv1;
            *(float2*)&arow[c]                 = make_float2(p0, p1);
            *(float2*)&arow[(size_t)8 * S + c] = make_float2(p2, p3);
            pp[nt][0] = pack2(p0, p1);
            pp[nt][1] = pack2(p2, p3);
        }

        // ── O += Pnorm*Vh (already normalized: no epilogue divide) ──
        #pragma unroll
        for (int ks = 0; ks < 4; ks++) {
            uint32_t ph[4] = { pp[2*ks][0], pp[2*ks][1], pp[2*ks+1][0], pp[2*ks+1][1] };
            uint32_t va = sbase + (uint32_t)OFF_V * 2 + cb + voff + (uint32_t)(16 * ks * PIT) * 2;
            #pragma unroll
            for (int np = 0; np < 4; np++) {
                uint32_t vh[4];
                ldsm4t(vh, va + 32 * np);
                mma16816(oacc[2*np  ], ph, vh[0], vh[1]);
                mma16816(oacc[2*np+1], ph, vh[2], vh[3]);
            }
        }

        __syncthreads();
        if (kt + 2 < NKT) issue_kv(kt + 2, kt & 1);
        CP_COMMIT();
    }

    // ── write O (already normalized) ──
    float* or0 = out + gr0 * D;
    float* or1 = out + (gr0 + 8) * D;
    #pragma unroll
    for (int nt = 0; nt < 8; nt++) {
        int c = nt * 8 + 2 * tg;
        *(float2*)&or0[c] = make_float2(oacc[nt][0], oacc[nt][1]);
        *(float2*)&or1[c] = make_float2(oacc[nt][2], oacc[nt][3]);
    }
}

extern "C" void kernel_launch(void* const* d_in, const int* in_sizes, int n_in,
                              void* d_out, int out_size)
{
    const float* q    = (const float*)d_in[0];
    const float* k    = (const float*)d_in[1];
    const float* v    = (const float*)d_in[2];
    const int*   mask = (const int*)d_in[3];
    float* out  = (float*)d_out;
    float* attn = out + (size_t)B * H * S * D;           // tuple: (output, attn)

    cudaFuncSetAttribute(lpass,     cudaFuncAttributeMaxDynamicSharedMemorySize, SMEM_L_BYTES);
    cudaFuncSetAttribute(attn_norm, cudaFuncAttributeMaxDynamicSharedMemorySize, SMEM_BYTES);

    preconv<<<(unsigned)(NE / 4 / 256), 256>>>((const float4*)q, (const float4*)k,
                                               (const float4*)v);
    dim3 grid(H, S / TQ, B);   // h fastest: CTAs share mask tiles in L2
    lpass<<<grid, 256, SMEM_L_BYTES>>>(mask);
    attn_norm<<<grid, 256, SMEM_BYTES>>>(mask, out, attn);
}